// round 16
// baseline (speedup 1.0000x reference)
#include <cuda_runtime.h>
#include <cuda_bf16.h>
#include <cuda_fp16.h>
#include <cstdint>

#define NN   65536
#define SS   128
#define DIN  512
#define HH   1024
#define DOUTT 256

// ---------------- static device scratch ----------------
__device__ float g_u[NN];
__device__ float g_v2[HH];
__device__ float g_c;
__device__ float g_gram_part[128 * 128 * 128];
__device__ float g_y_part[512 * 128];
__device__ float g_G[128 * 128];
__device__ float g_y[128];
__device__ float g_wprime[128];
__device__ __half g_w1T[(size_t)HH * DIN];   // W1^T in fp16, [n][k]

// ---------------- helpers (baseline PTX only — must compile for plain sm_103) ----------------
__device__ __forceinline__ uint32_t smem_u32(const void* p) {
    uint32_t a;
    asm("{ .reg .u64 t; cvta.to.shared.u64 t, %1; cvt.u32.u64 %0, t; }" : "=r"(a) : "l"(p));
    return a;
}
__device__ __forceinline__ void cp16(uint32_t dst, const void* src) {
    asm volatile("cp.async.cg.shared.global [%0], [%1], 16;" :: "r"(dst), "l"(src));
}
#define CP_COMMIT() asm volatile("cp.async.commit_group;" ::: "memory")
#define CP_WAIT0()  asm volatile("cp.async.wait_group 0;" ::: "memory")

__device__ __forceinline__ void mma_f16(float* c, const uint32_t* a, const uint32_t* b) {
    asm volatile("mma.sync.aligned.m16n8k16.row.col.f32.f16.f16.f32 "
        "{%0,%1,%2,%3}, {%4,%5,%6,%7}, {%8,%9}, {%0,%1,%2,%3};"
        : "+f"(c[0]), "+f"(c[1]), "+f"(c[2]), "+f"(c[3])
        : "r"(a[0]), "r"(a[1]), "r"(a[2]), "r"(a[3]), "r"(b[0]), "r"(b[1]));
}
__device__ __forceinline__ void ldm_x4(uint32_t* r, uint32_t addr) {
    asm volatile("ldmatrix.sync.aligned.m8n8.x4.shared.b16 {%0,%1,%2,%3}, [%4];"
        : "=r"(r[0]), "=r"(r[1]), "=r"(r[2]), "=r"(r[3]) : "r"(addr));
}
// pack two fp32 -> fp16x2 word (rn); %1 -> high half, %2 -> low half
__device__ __forceinline__ uint32_t cvt2h(float hi, float lo) {
    uint32_t r;
    asm("cvt.rn.f16x2.f32 %0, %1, %2;" : "=r"(r) : "f"(hi), "f"(lo));
    return r;
}

// ---------------- K0: W1 -> transposed fp16 [n][k] ----------------
__global__ void k_cvt_w1(const float* __restrict__ W1) {
    __shared__ float t[32][33];
    const int tx = threadIdx.x, ty = threadIdx.y;       // 32 x 8
    const int n0 = blockIdx.x * 32, k0 = blockIdx.y * 32;
#pragma unroll
    for (int i = 0; i < 4; i++)
        t[ty + i * 8][tx] = W1[(size_t)(k0 + ty + i * 8) * HH + n0 + tx];
    __syncthreads();
#pragma unroll
    for (int i = 0; i < 4; i++) {
        const int n = n0 + ty + i * 8, k = k0 + tx;
        g_w1T[(size_t)n * DIN + k] = __float2half_rn(t[tx][ty + i * 8]);
    }
}

// ---------------- K1: v2 = W2 @ w_deep, c = b2 . w_deep ----------------
__global__ void k_prep(const float* __restrict__ W2,
                       const float* __restrict__ w_deep,
                       const float* __restrict__ b2) {
    int h = blockIdx.x * blockDim.x + threadIdx.x;
    if (h < HH) {
        float acc = 0.f;
        const float* row = W2 + (size_t)h * DOUTT;
#pragma unroll 8
        for (int d = 0; d < DOUTT; d++) acc = fmaf(row[d], w_deep[d], acc);
        g_v2[h] = acc;
    }
    if (blockIdx.x == 0 && threadIdx.x == 0) {
        float c = 0.f;
        for (int d = 0; d < DOUTT; d++) c = fmaf(b2[d], w_deep[d], c);
        g_c = c;
    }
}

// ---------------- K2: fp16 mma.sync MLP with A resident in smem, fused u/y ----------------
// 256 threads = 8 warps (4m x 2n), warp tile 32x64, BM=128, BN=128.
// A: full-K fp16 tile 128 x 512 halves, row stride 260 words (520 halves), converted
// ONCE in prologue. B: fp16 W1^T tiles (128 x 32 halves, stride 20 words), double-buffered.
// Word offsets:
#define T_A    0                       // 128 * 260 = 33280 words (133 KB)
#define T_B0   33280
#define T_B1   35840
#define W_B1S  38400
#define W_V2S  39424
#define W_RED  40448
#define W_US   41472
#define MLP_SMEM_BYTES ((41472 + 192) * 4)

__device__ __forceinline__ void load_b(uint32_t sb, uint32_t bufw,
                                       int kbase, int nbase, int tid) {
    // 128 rows x 32 halves = 512 16B chunks -> 2/thread
#pragma unroll
    for (int c = 0; c < 2; c++) {
        const int id = c * 256 + tid;
        const int row = id >> 2, col = id & 3;
        cp16(sb + (bufw + row * 20 + col * 4) * 4,
             (const char*)g_w1T + ((size_t)(nbase + row) * DIN + kbase + col * 8) * 2);
    }
}

__global__ __launch_bounds__(256, 1)
void k_mlp(const float* __restrict__ d1, const float* __restrict__ b1,
           const float* __restrict__ S) {
    extern __shared__ float smf[];
    uint32_t* smw = (uint32_t*)smf;
    const uint32_t sb = smem_u32(smf);
    const int tid = threadIdx.x, wid = tid >> 5, lane = tid & 31;
    const int wm = wid >> 1, wn = wid & 1;       // warp grid 4 x 2
    const int mbase = blockIdx.x * 128;
    const int lq = lane >> 2, lr = lane & 3;

    float* b1s = smf + W_B1S;
    float* v2s = smf + W_V2S;
    for (int i = tid; i < HH; i += 256) { b1s[i] = b1[i]; v2s[i] = g_v2[i]; }

    // ---- prologue: convert d1 tile fp32 -> fp16 A-resident (once) ----
    {
        const float4* srcb = (const float4*)(d1 + (size_t)mbase * DIN);
#pragma unroll 4
        for (int c = 0; c < 64; c++) {
            const int id = c * 256 + tid;
            const int row = id >> 7, col4 = id & 127;   // fully coalesced LDG.128
            const float4 v = srcb[row * 128 + col4];
            const uint32_t w0 = cvt2h(v.y, v.x);
            const uint32_t w1 = cvt2h(v.w, v.z);
            *(uint2*)(smw + T_A + row * 260 + col4 * 2) = make_uint2(w0, w1);
        }
    }
    __syncthreads();

    // ldmatrix per-lane addresses
    const int l8 = lane & 7, g = lane >> 3;
    // A x4: rows (wm*32 + (g&1)*8 + l8), k-halves group (g>>1)*8
    const uint32_t aw = (uint32_t)((wm * 32 + (g & 1) * 8 + l8) * 260 + (g >> 1) * 4);
    // B x4 (stride 20): rows n-blocks, k groups
    const uint32_t bw = (uint32_t)((wn * 64 + (g >> 1) * 8 + l8) * 20 + (g & 1) * 4);
    const uint32_t boff[2] = {T_B0, T_B1};

    float upart[4] = {0.f, 0.f, 0.f, 0.f};

    for (int nc = 0; nc < 8; nc++) {
        const int nbase = nc * 128;
        float c[2][8][4];
#pragma unroll
        for (int mt = 0; mt < 2; mt++)
#pragma unroll
            for (int nt = 0; nt < 8; nt++)
#pragma unroll
                for (int i = 0; i < 4; i++) c[mt][nt][i] = 0.f;

        load_b(sb, T_B0, 0, nbase, tid);
        CP_COMMIT();

        for (int kt = 0; kt < 16; kt++) {
            const int cur = kt & 1, nxt = cur ^ 1;
            CP_WAIT0();
            __syncthreads();
            if (kt < 15) {
                load_b(sb, boff[nxt], (kt + 1) * 32, nbase, tid);
                CP_COMMIT();
            }
            const uint32_t Aad = sb + (T_A + aw + (uint32_t)kt * 16) * 4;
            const uint32_t Bb  = sb + (boff[cur] + bw) * 4;
#pragma unroll
            for (int ks = 0; ks < 2; ks++) {
                const uint32_t ko = (uint32_t)ks * 32;   // 8 words = 16 halves
                uint32_t ah[2][4], bb[4][4];
                ldm_x4(ah[0], Aad + ko);
                ldm_x4(ah[1], Aad + 16640 + ko);         // +16 rows = 16*260 words
#pragma unroll
                for (int p = 0; p < 4; p++)
                    ldm_x4(bb[p], Bb + (uint32_t)p * 1280 + ko);
#pragma unroll
                for (int mt = 0; mt < 2; mt++)
#pragma unroll
                    for (int p = 0; p < 4; p++) {
                        mma_f16(c[mt][2 * p],     ah[mt], &bb[p][0]);
                        mma_f16(c[mt][2 * p + 1], ah[mt], &bb[p][2]);
                    }
            }
        }
        // fused epilogue: upart += relu(c + b1) . v2
#pragma unroll
        for (int mt = 0; mt < 2; mt++)
#pragma unroll
            for (int nt = 0; nt < 8; nt++) {
                const int col0 = nbase + wn * 64 + nt * 8 + 2 * lr;
                const float b1a = b1s[col0], b1b = b1s[col0 + 1];
                const float v2a = v2s[col0], v2b = v2s[col0 + 1];
                upart[0 + mt * 2] = fmaf(fmaxf(c[mt][nt][0] + b1a, 0.f), v2a, upart[0 + mt * 2]);
                upart[0 + mt * 2] = fmaf(fmaxf(c[mt][nt][1] + b1b, 0.f), v2b, upart[0 + mt * 2]);
                upart[1 + mt * 2] = fmaf(fmaxf(c[mt][nt][2] + b1a, 0.f), v2a, upart[1 + mt * 2]);
                upart[1 + mt * 2] = fmaf(fmaxf(c[mt][nt][3] + b1b, 0.f), v2b, upart[1 + mt * 2]);
            }
        __syncthreads();  // before next nc refills B buffers
    }

    // reduce 8 column-partials per row (deterministic), store u, then y partial
    float* red = smf + W_RED;   // [128][8]
    float* us  = smf + W_US;    // [128]
#pragma unroll
    for (int mt = 0; mt < 2; mt++)
#pragma unroll
        for (int hh = 0; hh < 2; hh++) {
            const int row = wm * 32 + mt * 16 + hh * 8 + lq;
            red[row * 8 + wn * 4 + lr] = upart[mt * 2 + hh];
        }
    __syncthreads();
    if (tid < 128) {
        float s = 0.f;
#pragma unroll
        for (int t = 0; t < 8; t++) s += red[tid * 8 + t];
        const float u = s + g_c;
        g_u[mbase + tid] = u;
        us[tid] = u;
    }
    __syncthreads();
    if (tid < 128) {
        float acc = 0.f;
#pragma unroll 8
        for (int r = 0; r < 128; r++)
            acc = fmaf(S[(size_t)(mbase + r) * SS + tid], us[r], acc);
        g_y_part[blockIdx.x * 128 + tid] = acc;
    }
}

// ---------------- K3: Gram partials (FFMA), 128 CTAs x 512 rows ----------------
__global__ __launch_bounds__(256) void k_gram(const float* __restrict__ Smat) {
    __shared__ __align__(16) float Srow[8][128];
    const int tid = threadIdx.x;
    const int tx = tid & 15, ty = tid >> 4;
    const int i0 = ty * 8, j0 = tx * 8;
    const int base = blockIdx.x * 512;
    const int lr = tid >> 5;
    const int lc = (tid & 31) * 4;

    float acc[8][8];
#pragma unroll
    for (int i = 0; i < 8; i++)
#pragma unroll
        for (int j = 0; j < 8; j++) acc[i][j] = 0.f;

    for (int st = 0; st < 64; st++) {
        __syncthreads();
        *(float4*)&Srow[lr][lc] = *(const float4*)&Smat[(size_t)(base + st * 8 + lr) * SS + lc];
        __syncthreads();
#pragma unroll
        for (int r = 0; r < 8; r++) {
            float a[8], b[8];
            *(float4*)&a[0] = *(float4*)&Srow[r][i0];
            *(float4*)&a[4] = *(float4*)&Srow[r][i0 + 4];
            *(float4*)&b[0] = *(float4*)&Srow[r][j0];
            *(float4*)&b[4] = *(float4*)&Srow[r][j0 + 4];
#pragma unroll
            for (int i = 0; i < 8; i++)
#pragma unroll
                for (int j = 0; j < 8; j++)
                    acc[i][j] = fmaf(a[i], b[j], acc[i][j]);
        }
    }
    float* outp = g_gram_part + (size_t)blockIdx.x * 128 * 128;
#pragma unroll
    for (int i = 0; i < 8; i++)
#pragma unroll
        for (int j = 0; j < 8; j++)
            outp[(i0 + i) * 128 + (j0 + j)] = acc[i][j];
}

// ---------------- K4: reduce partials, 4 threads per output (fixed-order tree) ----------------
__global__ __launch_bounds__(256) void k_reduce() {
    __shared__ float p[256];
    const int tid = threadIdx.x;
    const int il = tid >> 2;
    const int part = tid & 3;
    const int idx = blockIdx.x * 64 + il;

    {   // Gram: 128 partials -> 4 chunks of 32, fixed order
        float s = 0.f;
        const int b0 = part * 32;
        for (int b = 0; b < 32; b++)
            s += g_gram_part[(size_t)(b0 + b) * 16384 + idx];
        p[tid] = s;
    }
    __syncthreads();
    if (part == 0)
        g_G[idx] = p[il * 4] + p[il * 4 + 1] + p[il * 4 + 2] + p[il * 4 + 3];
    __syncthreads();
    if (blockIdx.x == 0) {
        const int j = tid >> 1;
        const int half = tid & 1;
        float s = 0.f;
        const int b0 = half * 256;
        for (int b = 0; b < 256; b++)
            s += g_y_part[(b0 + b) * 128 + j];
        p[tid] = s;
        __syncthreads();
        if (half == 0) g_y[j] = p[j * 2] + p[j * 2 + 1];
    }
}

// ---------------- K5: Richardson solve G z = y ----------------
__global__ void k_solve(const float* __restrict__ w_struct) {
    __shared__ float zs[128];
    const int i = threadIdx.x;
    const float invN = 1.0f / (float)NN;
    const float yi = g_y[i];
    zs[i] = yi * invN;
    __syncthreads();
    for (int it = 0; it < 30; it++) {
        float gz = 0.f;
        const float* Gi = g_G + i * 128;
#pragma unroll 8
        for (int j = 0; j < 128; j++) gz = fmaf(Gi[j], zs[j], gz);
        const float znew = zs[i] + (yi - gz) * invN;
        __syncthreads();
        zs[i] = znew;
        __syncthreads();
    }
    g_wprime[i] = w_struct[i] - zs[i];
}

// ---------------- K6: out[n] = u[n] + S[n,:] . wprime ----------------
__global__ __launch_bounds__(256) void k_final(const float* __restrict__ Smat,
                                               float* __restrict__ out) {
    __shared__ float wp[128];
    const int tid = threadIdx.x;
    if (tid < 128) wp[tid] = g_wprime[tid];
    __syncthreads();
    const int warp = tid >> 5, lane = tid & 31;
    const int row = blockIdx.x * 8 + warp;
    const float4 a = *(const float4*)&Smat[(size_t)row * SS + lane * 4];
    const float4 w = *(const float4*)&wp[lane * 4];
    float s = a.x * w.x + a.y * w.y + a.z * w.z + a.w * w.w;
#pragma unroll
    for (int off = 16; off; off >>= 1) s += __shfl_xor_sync(0xffffffffu, s, off);
    if (lane == 0) out[row] = g_u[row] + s;
}

// ---------------- launch ----------------
extern "C" void kernel_launch(void* const* d_in, const int* in_sizes, int n_in,
                              void* d_out, int out_size) {
    const float* structured = (const float*)d_in[0];
    const float* d1         = (const float*)d_in[1];
    const float* W1         = (const float*)d_in[2];
    const float* b1         = (const float*)d_in[3];
    const float* W2         = (const float*)d_in[4];
    const float* b2         = (const float*)d_in[5];
    const float* w_struct   = (const float*)d_in[6];
    const float* w_deep     = (const float*)d_in[7];
    float* out = (float*)d_out;
    (void)in_sizes; (void)n_in; (void)out_size;

    cudaFuncSetAttribute(k_mlp, cudaFuncAttributeMaxDynamicSharedMemorySize, MLP_SMEM_BYTES);

    k_prep  <<<4, 256>>>(W2, w_deep, b2);
    k_cvt_w1<<<dim3(32, 16), dim3(32, 8)>>>(W1);
    k_mlp   <<<NN / 128, 256, MLP_SMEM_BYTES>>>(d1, b1, structured);
    k_gram  <<<128, 256>>>(structured);
    k_reduce<<<256, 256>>>();
    k_solve <<<1, 128>>>(w_struct);
    k_final <<<NN / 8, 256>>>(structured, out);
}

// round 17
// speedup vs baseline: 1.4740x; 1.4740x over previous
#include <cuda_runtime.h>
#include <cuda_bf16.h>
#include <cuda_fp16.h>
#include <cstdint>

#define NN   65536
#define SS   128
#define DIN  512
#define HH   1024
#define DOUTT 256

// ---------------- static device scratch ----------------
__device__ float g_u[NN];
__device__ float g_v2[HH];
__device__ float g_c;
__device__ float g_gram_part[512 * 128 * 128];
__device__ float g_y_part[512 * 128];
__device__ float g_G[128 * 128];
__device__ float g_y[128];
__device__ float g_wprime[128];
__device__ __half g_w1T[(size_t)HH * DIN];   // W1^T in fp16, [n][k]

// ---------------- helpers (baseline PTX only — must compile for plain sm_103) ----------------
__device__ __forceinline__ uint32_t smem_u32(const void* p) {
    uint32_t a;
    asm("{ .reg .u64 t; cvta.to.shared.u64 t, %1; cvt.u32.u64 %0, t; }" : "=r"(a) : "l"(p));
    return a;
}
__device__ __forceinline__ void cp16(uint32_t dst, const void* src) {
    asm volatile("cp.async.cg.shared.global [%0], [%1], 16;" :: "r"(dst), "l"(src));
}
#define CP_COMMIT() asm volatile("cp.async.commit_group;" ::: "memory")
#define CP_WAIT0()  asm volatile("cp.async.wait_group 0;" ::: "memory")

__device__ __forceinline__ void mma_f16(float* c, const uint32_t* a, const uint32_t* b) {
    asm volatile("mma.sync.aligned.m16n8k16.row.col.f32.f16.f16.f32 "
        "{%0,%1,%2,%3}, {%4,%5,%6,%7}, {%8,%9}, {%0,%1,%2,%3};"
        : "+f"(c[0]), "+f"(c[1]), "+f"(c[2]), "+f"(c[3])
        : "r"(a[0]), "r"(a[1]), "r"(a[2]), "r"(a[3]), "r"(b[0]), "r"(b[1]));
}
__device__ __forceinline__ void ldm_x4(uint32_t* r, uint32_t addr) {
    asm volatile("ldmatrix.sync.aligned.m8n8.x4.shared.b16 {%0,%1,%2,%3}, [%4];"
        : "=r"(r[0]), "=r"(r[1]), "=r"(r[2]), "=r"(r[3]) : "r"(addr));
}
// pack two fp32 -> fp16x2 word (rn); %1 -> high half, %2 -> low half
__device__ __forceinline__ uint32_t cvt2h(float hi, float lo) {
    uint32_t r;
    asm("cvt.rn.f16x2.f32 %0, %1, %2;" : "=r"(r) : "f"(hi), "f"(lo));
    return r;
}

// ---------------- K0: W1 -> transposed fp16 [n][k] ----------------
__global__ void k_cvt_w1(const float* __restrict__ W1) {
    __shared__ float t[32][33];
    const int tx = threadIdx.x, ty = threadIdx.y;       // 32 x 8
    const int n0 = blockIdx.x * 32, k0 = blockIdx.y * 32;
#pragma unroll
    for (int i = 0; i < 4; i++)
        t[ty + i * 8][tx] = W1[(size_t)(k0 + ty + i * 8) * HH + n0 + tx];
    __syncthreads();
#pragma unroll
    for (int i = 0; i < 4; i++) {
        const int n = n0 + ty + i * 8, k = k0 + tx;
        g_w1T[(size_t)n * DIN + k] = __float2half_rn(t[tx][ty + i * 8]);
    }
}

// ---------------- K1: v2 = W2 @ w_deep, c = b2 . w_deep ----------------
__global__ void k_prep(const float* __restrict__ W2,
                       const float* __restrict__ w_deep,
                       const float* __restrict__ b2) {
    int h = blockIdx.x * blockDim.x + threadIdx.x;
    if (h < HH) {
        float acc = 0.f;
        const float* row = W2 + (size_t)h * DOUTT;
#pragma unroll 8
        for (int d = 0; d < DOUTT; d++) acc = fmaf(row[d], w_deep[d], acc);
        g_v2[h] = acc;
    }
    if (blockIdx.x == 0 && threadIdx.x == 0) {
        float c = 0.f;
        for (int d = 0; d < DOUTT; d++) c = fmaf(b2[d], w_deep[d], c);
        g_c = c;
    }
}

// ---------------- K2: fp16 mma.sync MLP, A resident, 512 threads ----------------
// 16 warps (4m x 4n), warp tile 32x32, BM=128, BN=128.
// A: full-K fp16 tile 128 x 512 halves, row stride 260 words, converted ONCE.
// B: fp16 W1^T tiles (128 x 32 halves, stride 20 words), double-buffered cp.async.
// Word offsets:
#define T_A    0                       // 128 * 260 = 33280 words (133 KB)
#define T_B0   33280
#define T_B1   35840
#define W_B1S  38400
#define W_V2S  39424
#define W_RED  40448                   // [128][16]
#define W_US   42496
#define MLP_SMEM_BYTES ((42496 + 192) * 4)

__device__ __forceinline__ void load_b(uint32_t sb, uint32_t bufw,
                                       int kbase, int nbase, int tid) {
    // 128 rows x 32 halves = 512 16B chunks -> 1/thread
    const int row = tid >> 2, col = tid & 3;
    cp16(sb + (bufw + row * 20 + col * 4) * 4,
         (const char*)g_w1T + ((size_t)(nbase + row) * DIN + kbase + col * 8) * 2);
}

__global__ __launch_bounds__(512, 1)
void k_mlp(const float* __restrict__ d1, const float* __restrict__ b1,
           const float* __restrict__ S) {
    extern __shared__ float smf[];
    uint32_t* smw = (uint32_t*)smf;
    const uint32_t sb = smem_u32(smf);
    const int tid = threadIdx.x, wid = tid >> 5, lane = tid & 31;
    const int wm = wid >> 2, wn = wid & 3;       // warp grid 4 x 4
    const int mbase = blockIdx.x * 128;
    const int lq = lane >> 2, lr = lane & 3;

    float* b1s = smf + W_B1S;
    float* v2s = smf + W_V2S;
    for (int i = tid; i < HH; i += 512) { b1s[i] = b1[i]; v2s[i] = g_v2[i]; }

    // ---- prologue: convert d1 tile fp32 -> fp16 A-resident (once) ----
    {
        const float4* srcb = (const float4*)(d1 + (size_t)mbase * DIN);
#pragma unroll 4
        for (int c = 0; c < 32; c++) {
            const int id = c * 512 + tid;
            const int row = id >> 7, col4 = id & 127;   // fully coalesced LDG.128
            const float4 v = srcb[row * 128 + col4];
            const uint32_t w0 = cvt2h(v.y, v.x);
            const uint32_t w1 = cvt2h(v.w, v.z);
            *(uint2*)(smw + T_A + row * 260 + col4 * 2) = make_uint2(w0, w1);
        }
    }
    __syncthreads();

    // ldmatrix per-lane addresses
    const int l8 = lane & 7, g = lane >> 3;
    const uint32_t aw = (uint32_t)((wm * 32 + (g & 1) * 8 + l8) * 260 + (g >> 1) * 4);
    const uint32_t bw = (uint32_t)((wn * 32 + (g >> 1) * 8 + l8) * 20 + (g & 1) * 4);
    const uint32_t boff[2] = {T_B0, T_B1};

    float upart[4] = {0.f, 0.f, 0.f, 0.f};

    for (int nc = 0; nc < 8; nc++) {
        const int nbase = nc * 128;
        float c[2][4][4];
#pragma unroll
        for (int mt = 0; mt < 2; mt++)
#pragma unroll
            for (int nt = 0; nt < 4; nt++)
#pragma unroll
                for (int i = 0; i < 4; i++) c[mt][nt][i] = 0.f;

        load_b(sb, T_B0, 0, nbase, tid);
        CP_COMMIT();

        for (int kt = 0; kt < 16; kt++) {
            const int cur = kt & 1, nxt = cur ^ 1;
            CP_WAIT0();
            __syncthreads();
            if (kt < 15) {
                load_b(sb, boff[nxt], (kt + 1) * 32, nbase, tid);
                CP_COMMIT();
            }
            const uint32_t Aad = sb + (T_A + aw + (uint32_t)kt * 16) * 4;
            const uint32_t Bb  = sb + (boff[cur] + bw) * 4;
#pragma unroll
            for (int ks = 0; ks < 2; ks++) {
                const uint32_t ko = (uint32_t)ks * 32;   // 8 words = 16 halves
                uint32_t ah[2][4], bb[2][4];
                ldm_x4(ah[0], Aad + ko);
                ldm_x4(ah[1], Aad + 16640 + ko);         // +16 rows = 16*260 words
#pragma unroll
                for (int p = 0; p < 2; p++)
                    ldm_x4(bb[p], Bb + (uint32_t)p * 1280 + ko);   // +16 n-rows
#pragma unroll
                for (int mt = 0; mt < 2; mt++)
#pragma unroll
                    for (int p = 0; p < 2; p++) {
                        mma_f16(c[mt][2 * p],     ah[mt], &bb[p][0]);
                        mma_f16(c[mt][2 * p + 1], ah[mt], &bb[p][2]);
                    }
            }
        }
        // fused epilogue: upart += relu(c + b1) . v2
#pragma unroll
        for (int mt = 0; mt < 2; mt++)
#pragma unroll
            for (int nt = 0; nt < 4; nt++) {
                const int col0 = nbase + wn * 32 + nt * 8 + 2 * lr;
                const float b1a = b1s[col0], b1b = b1s[col0 + 1];
                const float v2a = v2s[col0], v2b = v2s[col0 + 1];
                upart[0 + mt * 2] = fmaf(fmaxf(c[mt][nt][0] + b1a, 0.f), v2a, upart[0 + mt * 2]);
                upart[0 + mt * 2] = fmaf(fmaxf(c[mt][nt][1] + b1b, 0.f), v2b, upart[0 + mt * 2]);
                upart[1 + mt * 2] = fmaf(fmaxf(c[mt][nt][2] + b1a, 0.f), v2a, upart[1 + mt * 2]);
                upart[1 + mt * 2] = fmaf(fmaxf(c[mt][nt][3] + b1b, 0.f), v2b, upart[1 + mt * 2]);
            }
        __syncthreads();  // before next nc refills B buffers
    }

    // reduce 16 column-partials per row (deterministic), store u, then y partial
    float* red = smf + W_RED;   // [128][16]
    float* us  = smf + W_US;    // [128]
#pragma unroll
    for (int mt = 0; mt < 2; mt++)
#pragma unroll
        for (int hh = 0; hh < 2; hh++) {
            const int row = wm * 32 + mt * 16 + hh * 8 + lq;
            red[row * 16 + wn * 4 + lr] = upart[mt * 2 + hh];
        }
    __syncthreads();
    if (tid < 128) {
        float s = 0.f;
#pragma unroll
        for (int t = 0; t < 16; t++) s += red[tid * 16 + t];
        const float u = s + g_c;
        g_u[mbase + tid] = u;
        us[tid] = u;
    }
    __syncthreads();
    if (tid < 128) {
        float acc = 0.f;
#pragma unroll 8
        for (int r = 0; r < 128; r++)
            acc = fmaf(S[(size_t)(mbase + r) * SS + tid], us[r], acc);
        g_y_part[blockIdx.x * 128 + tid] = acc;
    }
}

// ---------------- K3: Gram partials (FFMA), 512 CTAs x 128 rows ----------------
__global__ __launch_bounds__(256) void k_gram(const float* __restrict__ Smat) {
    __shared__ __align__(16) float Srow[8][128];
    const int tid = threadIdx.x;
    const int tx = tid & 15, ty = tid >> 4;
    const int i0 = ty * 8, j0 = tx * 8;
    const int base = blockIdx.x * 128;
    const int lr = tid >> 5;
    const int lc = (tid & 31) * 4;

    float acc[8][8];
#pragma unroll
    for (int i = 0; i < 8; i++)
#pragma unroll
        for (int j = 0; j < 8; j++) acc[i][j] = 0.f;

    for (int st = 0; st < 16; st++) {
        __syncthreads();
        *(float4*)&Srow[lr][lc] = *(const float4*)&Smat[(size_t)(base + st * 8 + lr) * SS + lc];
        __syncthreads();
#pragma unroll
        for (int r = 0; r < 8; r++) {
            float a[8], b[8];
            *(float4*)&a[0] = *(float4*)&Srow[r][i0];
            *(float4*)&a[4] = *(float4*)&Srow[r][i0 + 4];
            *(float4*)&b[0] = *(float4*)&Srow[r][j0];
            *(float4*)&b[4] = *(float4*)&Srow[r][j0 + 4];
#pragma unroll
            for (int i = 0; i < 8; i++)
#pragma unroll
                for (int j = 0; j < 8; j++)
                    acc[i][j] = fmaf(a[i], b[j], acc[i][j]);
        }
    }
    float* outp = g_gram_part + (size_t)blockIdx.x * 128 * 128;
#pragma unroll
    for (int i = 0; i < 8; i++)
#pragma unroll
        for (int j = 0; j < 8; j++)
            outp[(i0 + i) * 128 + (j0 + j)] = acc[i][j];
}

// ---------------- K4: reduce partials, 4 threads per output (fixed-order tree) ----------------
__global__ __launch_bounds__(256) void k_reduce() {
    __shared__ float p[256];
    const int tid = threadIdx.x;
    const int il = tid >> 2;
    const int part = tid & 3;
    const int idx = blockIdx.x * 64 + il;

    {   // Gram: 512 partials -> 4 chunks of 128, fixed order
        float s = 0.f;
        const int b0 = part * 128;
        for (int b = 0; b < 128; b++)
            s += g_gram_part[(size_t)(b0 + b) * 16384 + idx];
        p[tid] = s;
    }
    __syncthreads();
    if (part == 0)
        g_G[idx] = p[il * 4] + p[il * 4 + 1] + p[il * 4 + 2] + p[il * 4 + 3];
    __syncthreads();
    if (blockIdx.x == 0) {
        const int j = tid >> 1;
        const int half = tid & 1;
        float s = 0.f;
        const int b0 = half * 256;
        for (int b = 0; b < 256; b++)
            s += g_y_part[(b0 + b) * 128 + j];
        p[tid] = s;
        __syncthreads();
        if (half == 0) g_y[j] = p[j * 2] + p[j * 2 + 1];
    }
}

// ---------------- K5: Richardson solve G z = y ----------------
__global__ void k_solve(const float* __restrict__ w_struct) {
    __shared__ float zs[128];
    const int i = threadIdx.x;
    const float invN = 1.0f / (float)NN;
    const float yi = g_y[i];
    zs[i] = yi * invN;
    __syncthreads();
    for (int it = 0; it < 30; it++) {
        float gz = 0.f;
        const float* Gi = g_G + i * 128;
#pragma unroll 8
        for (int j = 0; j < 128; j++) gz = fmaf(Gi[j], zs[j], gz);
        const float znew = zs[i] + (yi - gz) * invN;
        __syncthreads();
        zs[i] = znew;
        __syncthreads();
    }
    g_wprime[i] = w_struct[i] - zs[i];
}

// ---------------- K6: out[n] = u[n] + S[n,:] . wprime ----------------
__global__ __launch_bounds__(256) void k_final(const float* __restrict__ Smat,
                                               float* __restrict__ out) {
    __shared__ float wp[128];
    const int tid = threadIdx.x;
    if (tid < 128) wp[tid] = g_wprime[tid];
    __syncthreads();
    const int warp = tid >> 5, lane = tid & 31;
    const int row = blockIdx.x * 8 + warp;
    const float4 a = *(const float4*)&Smat[(size_t)row * SS + lane * 4];
    const float4 w = *(const float4*)&wp[lane * 4];
    float s = a.x * w.x + a.y * w.y + a.z * w.z + a.w * w.w;
#pragma unroll
    for (int off = 16; off; off >>= 1) s += __shfl_xor_sync(0xffffffffu, s, off);
    if (lane == 0) out[row] = g_u[row] + s;
}

// ---------------- launch ----------------
extern "C" void kernel_launch(void* const* d_in, const int* in_sizes, int n_in,
                              void* d_out, int out_size) {
    const float* structured = (const float*)d_in[0];
    const float* d1         = (const float*)d_in[1];
    const float* W1         = (const float*)d_in[2];
    const float* b1         = (const float*)d_in[3];
    const float* W2         = (const float*)d_in[4];
    const float* b2         = (const float*)d_in[5];
    const float* w_struct   = (const float*)d_in[6];
    const float* w_deep     = (const float*)d_in[7];
    float* out = (float*)d_out;
    (void)in_sizes; (void)n_in; (void)out_size;

    cudaFuncSetAttribute(k_mlp, cudaFuncAttributeMaxDynamicSharedMemorySize, MLP_SMEM_BYTES);

    k_prep  <<<4, 256>>>(W2, w_deep, b2);
    k_cvt_w1<<<dim3(32, 16), dim3(32, 8)>>>(W1);
    k_mlp   <<<NN / 128, 512, MLP_SMEM_BYTES>>>(d1, b1, structured);
    k_gram  <<<512, 256>>>(structured);
    k_reduce<<<256, 256>>>();
    k_solve <<<1, 128>>>(w_struct);
    k_final <<<NN / 8, 256>>>(structured, out);
}